// round 10
// baseline (speedup 1.0000x reference)
#include <cuda_runtime.h>

// Problem constants (fixed by setup_inputs)
#define TWO_E   1600000
#define NE      800000
#define NN      50000
#define NBLK    (NN + 2*NE)          // 1,650,000 blocks total
#define NENT    (NBLK*16)            // 26,400,000 COO entries
#define SCAN_B  1024
#define NSB     ((NN + SCAN_B - 1)/SCAN_B)   // 49
#define MAXL    128                  // per-node capacity (Poisson(32): never exceeded)

// Key layout (u64):  node<<44 | t<<22 | cat<<20 | e
// g_diag: packed upper triangle of symmetric M^T M per node, 12 floats:
// [c00,c01,c02,c03, c11,c12,c13,c22, c23,c33, pad,pad]; tri(a<=b) = a*4+b-a*(a+1)/2

__device__ float                  g_diag[NN*12];
__device__ unsigned int           g_cnt[NN];
__device__ unsigned int           g_off[NN+1];
__device__ unsigned int           g_cur[NN];
__device__ unsigned long long     g_key[NBLK];
__device__ unsigned int           g_run[NBLK];       // (run_len<<16)|idx_in_run
__device__ unsigned int           g_partial[NSB];    // bit31 = ready flag, low bits = aggregate

// Per-edge M^T M scatter-add into packed triangle (v4+v4+v2 reductions),
// plus degree counting for the first E edges.
__global__ void k_diag_count(const float* __restrict__ maps,
                             const int*   __restrict__ ei) {
    int j = blockIdx.x * blockDim.x + threadIdx.x;
    if (j >= TWO_E) return;
    const float4* M = reinterpret_cast<const float4*>(maps + (size_t)j * 16);
    float4 r0 = M[0], r1 = M[1], r2 = M[2], r3 = M[3];
    float m[4][4] = {
        {r0.x, r0.y, r0.z, r0.w},
        {r1.x, r1.y, r1.z, r1.w},
        {r2.x, r2.y, r2.z, r2.w},
        {r3.x, r3.y, r3.z, r3.w}
    };
    int node = ei[j];
    float* tri = g_diag + (size_t)node * 12;

    float c00 = m[0][0]*m[0][0] + m[1][0]*m[1][0] + m[2][0]*m[2][0] + m[3][0]*m[3][0];
    float c01 = m[0][0]*m[0][1] + m[1][0]*m[1][1] + m[2][0]*m[2][1] + m[3][0]*m[3][1];
    float c02 = m[0][0]*m[0][2] + m[1][0]*m[1][2] + m[2][0]*m[2][2] + m[3][0]*m[3][2];
    float c03 = m[0][0]*m[0][3] + m[1][0]*m[1][3] + m[2][0]*m[2][3] + m[3][0]*m[3][3];
    float c11 = m[0][1]*m[0][1] + m[1][1]*m[1][1] + m[2][1]*m[2][1] + m[3][1]*m[3][1];
    float c12 = m[0][1]*m[0][2] + m[1][1]*m[1][2] + m[2][1]*m[2][2] + m[3][1]*m[3][2];
    float c13 = m[0][1]*m[0][3] + m[1][1]*m[1][3] + m[2][1]*m[2][3] + m[3][1]*m[3][3];
    float c22 = m[0][2]*m[0][2] + m[1][2]*m[1][2] + m[2][2]*m[2][2] + m[3][2]*m[3][2];
    float c23 = m[0][2]*m[0][3] + m[1][2]*m[1][3] + m[2][2]*m[2][3] + m[3][2]*m[3][3];
    float c33 = m[0][3]*m[0][3] + m[1][3]*m[1][3] + m[2][3]*m[2][3] + m[3][3]*m[3][3];

    asm volatile("red.global.add.v4.f32 [%0], {%1, %2, %3, %4};"
                 :: "l"(tri + 0), "f"(c00), "f"(c01), "f"(c02), "f"(c03) : "memory");
    asm volatile("red.global.add.v4.f32 [%0], {%1, %2, %3, %4};"
                 :: "l"(tri + 4), "f"(c11), "f"(c12), "f"(c13), "f"(c22) : "memory");
    asm volatile("red.global.add.v2.f32 [%0], {%1, %2};"
                 :: "l"(tri + 8), "f"(c23), "f"(c33) : "memory");

    if (j < NE) {
        atomicAdd(&g_cnt[node], 1u);
        atomicAdd(&g_cnt[ei[TWO_E + j]], 1u);
    }
}

// Single-pass exclusive scan over (cnt[i]+1) with decoupled lookback.
// 49 blocks, all co-resident (148 SMs) -> spin-wait is safe. Also seeds the
// diag key and fill cursor, and writes the grand total to g_off[NN].
__global__ void k_scan() {
    __shared__ unsigned sh[SCAN_B];
    __shared__ unsigned s_prefix;
    unsigned bid = blockIdx.x;
    unsigned i = bid * SCAN_B + threadIdx.x;
    unsigned v = (i < NN) ? (g_cnt[i] + 1u) : 0u;
    sh[threadIdx.x] = v;
    __syncthreads();
    for (int d = 1; d < SCAN_B; d <<= 1) {
        unsigned t = (threadIdx.x >= (unsigned)d) ? sh[threadIdx.x - d] : 0u;
        __syncthreads();
        sh[threadIdx.x] += t;
        __syncthreads();
    }
    if (threadIdx.x == 0) {
        unsigned total = sh[SCAN_B - 1];
        __threadfence();
        atomicExch(&g_partial[bid], 0x80000000u | total);   // publish aggregate
        unsigned p = 0;
        for (unsigned b = 0; b < bid; b++) {
            unsigned x;
            do { x = atomicAdd(&g_partial[b], 0u); } while (!(x & 0x80000000u));
            p += x & 0x7FFFFFFFu;
        }
        s_prefix = p;
    }
    __syncthreads();
    if (i < NN) {
        unsigned o = s_prefix + sh[threadIdx.x] - v;
        g_off[i] = o;
        g_key[o] = ((unsigned long long)i << 44) | ((unsigned long long)i << 22); // diag
        g_cur[i] = o + 1u;
        if (i == NN - 1) g_off[NN] = o + v;   // == NBLK
    }
}

// Fill edge blocks: cat1 under row[e] targeting col[e]; cat2 under col[e] targeting row[e].
__global__ void k_fill(const int* __restrict__ ei) {
    int e = blockIdx.x * blockDim.x + threadIdx.x;
    if (e >= NE) return;
    unsigned r = (unsigned)ei[e];
    unsigned c = (unsigned)ei[TWO_E + e];
    unsigned s1 = atomicAdd(&g_cur[r], 1u);
    g_key[s1] = ((unsigned long long)r << 44) | ((unsigned long long)c << 22)
              | (1ull << 20) | (unsigned long long)e;
    unsigned s2 = atomicAdd(&g_cur[c], 1u);
    g_key[s2] = ((unsigned long long)c << 44) | ((unsigned long long)r << 22)
              | (2ull << 20) | (unsigned long long)e;
}

// Warp-per-node rank sort with fused run detection.
__global__ void k_sort() {
    unsigned gw = (blockIdx.x * blockDim.x + threadIdx.x) >> 5;
    int lane = threadIdx.x & 31;
    int wloc = (int)(threadIdx.x >> 5);
    __shared__ unsigned long long sh[4][MAXL];
    if (gw >= NN) return;
    unsigned off = g_off[gw];
    int cnt = (int)(g_off[gw + 1] - off);

    if (cnt <= MAXL) {
        unsigned long long* buf = sh[wloc];
        for (int i = lane; i < cnt; i += 32) buf[i] = g_key[off + i];
        __syncwarp();
        for (int i = lane; i < cnt; i += 32) {
            unsigned long long x = buf[i];
            unsigned long long tx = x >> 22;
            int rank = 0; unsigned m = 0, j = 0;
            for (int q = 0; q < cnt; q++) {
                unsigned long long y = buf[q];
                bool lt = (y < x);
                bool eqt = ((y >> 22) == tx);
                rank += lt;
                m    += eqt;
                j    += (eqt && lt);
            }
            g_key[off + rank] = x;
            g_run[off + rank] = (m << 16) | j;
        }
    } else if (lane == 0) {
        // safety fallback; never triggers for this dataset
        for (int i = 1; i < cnt; i++) {
            unsigned long long x = g_key[off + i];
            int j = i - 1;
            while (j >= 0 && g_key[off + j] > x) { g_key[off + j + 1] = g_key[off + j]; j--; }
            g_key[off + j + 1] = x;
        }
        int i = 0;
        while (i < cnt) {
            unsigned long long t = g_key[off + i] >> 22;
            int j = i + 1;
            while (j < cnt && (g_key[off + j] >> 22) == t) j++;
            unsigned m = (unsigned)(j - i);
            for (int q = i; q < j; q++)
                g_run[off + q] = (m << 16) | (unsigned)(q - i);
            i = j;
        }
    }
}

// Emit: ONE thread per block slot. Loads key/off/run once, computes the full
// 4x4 tile, and writes 12 float4 stores (rows/cols/vals x 4 output rows).
// For a fixed output row a, consecutive lanes (consecutive slots) store
// contiguously -> 512B per warp store instruction within a node run.
__global__ void k_emit(const float* __restrict__ maps,
                       float* __restrict__ out) {
    unsigned s = blockIdx.x * blockDim.x + threadIdx.x;
    if (s >= (unsigned)NBLK) return;

    unsigned long long key = g_key[s];
    unsigned node = (unsigned)(key >> 44);
    unsigned t    = (unsigned)(key >> 22) & 0x3FFFFFu;
    int      cat  = (int)((key >> 20) & 3ull);
    unsigned e    = (unsigned)(key & 0xFFFFFull);

    unsigned off = g_off[node];
    unsigned cnt = g_off[node + 1] - off;
    unsigned k   = s - off;

    float tile[4][4];          // tile[a][b]
    if (cat == 0) {
        float tr[10];
        const float* tri = g_diag + (size_t)node * 12;
#pragma unroll
        for (int q = 0; q < 10; q++) tr[q] = tri[q];
#pragma unroll
        for (int a = 0; a < 4; a++)
#pragma unroll
            for (int b = 0; b < 4; b++) {
                int i2 = a < b ? a : b;
                int j2 = a < b ? b : a;
                tile[a][b] = tr[i2*4 + j2 - ((i2*(i2+1)) >> 1)];
            }
    } else {
        const float4* L4 = reinterpret_cast<const float4*>(maps + (size_t)e * 16);
        const float4* R4 = reinterpret_cast<const float4*>(maps + (size_t)(NE + e) * 16);
        float4 l0 = L4[0], l1 = L4[1], l2 = L4[2], l3 = L4[3];
        float4 q0 = R4[0], q1 = R4[1], q2 = R4[2], q3 = R4[3];
        float sel[4][4] = {{l0.x,l0.y,l0.z,l0.w},{l1.x,l1.y,l1.z,l1.w},
                           {l2.x,l2.y,l2.z,l2.w},{l3.x,l3.y,l3.z,l3.w}};
        float mat[4][4] = {{q0.x,q0.y,q0.z,q0.w},{q1.x,q1.y,q1.z,q1.w},
                           {q2.x,q2.y,q2.z,q2.w},{q3.x,q3.y,q3.z,q3.w}};
        // cat1: tile[a][b] = -sum_r L[r][a]*R[r][b]; cat2: swap roles
        if (cat == 2) {
#pragma unroll
            for (int r = 0; r < 4; r++)
#pragma unroll
                for (int c = 0; c < 4; c++) {
                    float tmp = sel[r][c]; sel[r][c] = mat[r][c]; mat[r][c] = tmp;
                }
        }
#pragma unroll
        for (int a = 0; a < 4; a++)
#pragma unroll
            for (int b = 0; b < 4; b++)
                tile[a][b] = -(sel[0][a]*mat[0][b] + sel[1][a]*mat[1][b]
                             + sel[2][a]*mat[2][b] + sel[3][a]*mat[3][b]);
    }

    unsigned run = g_run[s];
    unsigned m = run >> 16;
    unsigned j = run & 0xFFFFu;
    float cb = (float)(t * 4u);

    if (m == 1u) {
        float4* rows = reinterpret_cast<float4*>(out);
        float4* cols = reinterpret_cast<float4*>(out + (size_t)NENT);
        float4* vals = reinterpret_cast<float4*>(out + (size_t)2 * NENT);
        float4 colv = make_float4(cb, cb + 1.0f, cb + 2.0f, cb + 3.0f);
#pragma unroll
        for (int a = 0; a < 4; a++) {
            unsigned g = off * 16u + (unsigned)a * cnt * 4u + k * 4u;   // 4-aligned
            float rowv = (float)(node * 4 + a);
            rows[g >> 2] = make_float4(rowv, rowv, rowv, rowv);
            cols[g >> 2] = colv;
            vals[g >> 2] = make_float4(tile[a][0], tile[a][1], tile[a][2], tile[a][3]);
        }
    } else {
        // rare path: blocks sharing t interleave by b with stride m
        unsigned k0 = k - j;
        float* rows = out;
        float* cols = out + (size_t)NENT;
        float* vals = out + (size_t)2 * NENT;
#pragma unroll
        for (int a = 0; a < 4; a++) {
            size_t base = (size_t)off * 16u + (size_t)a * cnt * 4u + (size_t)k0 * 4u + j;
            float rowv = (float)(node * 4 + a);
#pragma unroll
            for (unsigned b = 0; b < 4; b++) {
                size_t pos = base + (size_t)b * m;
                rows[pos] = rowv;
                cols[pos] = cb + (float)b;
                vals[pos] = tile[a][b];
            }
        }
    }
}

extern "C" void kernel_launch(void* const* d_in, const int* in_sizes, int n_in,
                              void* d_out, int out_size) {
    const float* maps = (const float*)d_in[0];
    const int*   ei   = (const int*)d_in[1];
    float*       out  = (float*)d_out;

    void *p_diag, *p_cnt, *p_partial;
    cudaGetSymbolAddress(&p_diag, g_diag);
    cudaGetSymbolAddress(&p_cnt, g_cnt);
    cudaGetSymbolAddress(&p_partial, g_partial);
    cudaMemsetAsync(p_diag, 0, sizeof(float) * NN * 12);
    cudaMemsetAsync(p_cnt, 0, sizeof(unsigned) * NN);
    cudaMemsetAsync(p_partial, 0, sizeof(unsigned) * NSB);

    k_diag_count<<<(TWO_E + 255)/256, 256>>>(maps, ei);
    k_scan      <<<NSB, SCAN_B>>>();
    k_fill      <<<(NE + 255)/256, 256>>>(ei);
    k_sort      <<<(NN*32 + 127)/128, 128>>>();
    k_emit      <<<(NBLK + 255)/256, 256>>>(maps, out);
    (void)in_sizes; (void)n_in; (void)out_size;
}

// round 11
// speedup vs baseline: 1.2156x; 1.2156x over previous
#include <cuda_runtime.h>

// Problem constants (fixed by setup_inputs)
#define TWO_E   1600000
#define NE      800000
#define NN      50000
#define NBLK    (NN + 2*NE)          // 1,650,000 blocks total
#define NENT    (NBLK*16)            // 26,400,000 COO entries
#define SCAN_B  1024
#define NSB     ((NN + SCAN_B - 1)/SCAN_B)   // 49
#define MAXL    128                  // per-node capacity (Poisson(32): never exceeded)

// Key layout (u64):  node<<44 | t<<22 | cat<<20 | e
// g_diag: packed upper triangle of symmetric M^T M per node, 12 floats:
// [c00,c01,c02,c03, c11,c12,c13,c22, c23,c33, pad,pad]; tri(a<=b) = a*4+b-a*(a+1)/2

__device__ float                  g_diag[NN*12];
__device__ unsigned int           g_cnt[NN];
__device__ unsigned int           g_off[NN+1];
__device__ unsigned int           g_cur[NN];
__device__ unsigned long long     g_key[NBLK];
__device__ unsigned int           g_run[NBLK];       // (run_len<<16)|idx_in_run
__device__ unsigned int           g_partial[NSB];    // raw per-block sums

// Per-edge M^T M scatter-add into packed triangle (v4+v4+v2 reductions),
// plus degree counting for the first E edges.
__global__ void k_diag_count(const float* __restrict__ maps,
                             const int*   __restrict__ ei) {
    int j = blockIdx.x * blockDim.x + threadIdx.x;
    if (j >= TWO_E) return;
    const float4* M = reinterpret_cast<const float4*>(maps + (size_t)j * 16);
    float4 r0 = M[0], r1 = M[1], r2 = M[2], r3 = M[3];
    float m[4][4] = {
        {r0.x, r0.y, r0.z, r0.w},
        {r1.x, r1.y, r1.z, r1.w},
        {r2.x, r2.y, r2.z, r2.w},
        {r3.x, r3.y, r3.z, r3.w}
    };
    int node = ei[j];
    float* tri = g_diag + (size_t)node * 12;

    float c00 = m[0][0]*m[0][0] + m[1][0]*m[1][0] + m[2][0]*m[2][0] + m[3][0]*m[3][0];
    float c01 = m[0][0]*m[0][1] + m[1][0]*m[1][1] + m[2][0]*m[2][1] + m[3][0]*m[3][1];
    float c02 = m[0][0]*m[0][2] + m[1][0]*m[1][2] + m[2][0]*m[2][2] + m[3][0]*m[3][2];
    float c03 = m[0][0]*m[0][3] + m[1][0]*m[1][3] + m[2][0]*m[2][3] + m[3][0]*m[3][3];
    float c11 = m[0][1]*m[0][1] + m[1][1]*m[1][1] + m[2][1]*m[2][1] + m[3][1]*m[3][1];
    float c12 = m[0][1]*m[0][2] + m[1][1]*m[1][2] + m[2][1]*m[2][2] + m[3][1]*m[3][2];
    float c13 = m[0][1]*m[0][3] + m[1][1]*m[1][3] + m[2][1]*m[2][3] + m[3][1]*m[3][3];
    float c22 = m[0][2]*m[0][2] + m[1][2]*m[1][2] + m[2][2]*m[2][2] + m[3][2]*m[3][2];
    float c23 = m[0][2]*m[0][3] + m[1][2]*m[1][3] + m[2][2]*m[2][3] + m[3][2]*m[3][3];
    float c33 = m[0][3]*m[0][3] + m[1][3]*m[1][3] + m[2][3]*m[2][3] + m[3][3]*m[3][3];

    asm volatile("red.global.add.v4.f32 [%0], {%1, %2, %3, %4};"
                 :: "l"(tri + 0), "f"(c00), "f"(c01), "f"(c02), "f"(c03) : "memory");
    asm volatile("red.global.add.v4.f32 [%0], {%1, %2, %3, %4};"
                 :: "l"(tri + 4), "f"(c11), "f"(c12), "f"(c13), "f"(c22) : "memory");
    asm volatile("red.global.add.v2.f32 [%0], {%1, %2};"
                 :: "l"(tri + 8), "f"(c23), "f"(c33) : "memory");

    if (j < NE) {
        atomicAdd(&g_cnt[node], 1u);
        atomicAdd(&g_cnt[ei[TWO_E + j]], 1u);
    }
}

// Scan phase 1: per-block exclusive scan over (cnt[i] + 1); raw block sums -> g_partial
__global__ void k_scan1() {
    __shared__ unsigned sh[SCAN_B];
    unsigned i = blockIdx.x * SCAN_B + threadIdx.x;
    unsigned v = (i < NN) ? (g_cnt[i] + 1u) : 0u;
    sh[threadIdx.x] = v;
    __syncthreads();
    for (int d = 1; d < SCAN_B; d <<= 1) {
        unsigned t = (threadIdx.x >= (unsigned)d) ? sh[threadIdx.x - d] : 0u;
        __syncthreads();
        sh[threadIdx.x] += t;
        __syncthreads();
    }
    if (i < NN) g_off[i] = sh[threadIdx.x] - v;     // exclusive within block
    if (threadIdx.x == SCAN_B - 1) g_partial[blockIdx.x] = sh[SCAN_B - 1];
}

// Scan phase 3 (full grid): each thread sums preceding block partials inline
// (<=48 L1-broadcast loads). Also seeds diag key + fill cursor; last thread
// writes the grand total.
__global__ void k_scan3() {
    unsigned i = blockIdx.x * blockDim.x + threadIdx.x;
    if (i >= NN) return;
    unsigned nb = i >> 10;
    unsigned add = 0;
    for (unsigned b = 0; b < nb; b++) add += g_partial[b];
    unsigned o = g_off[i] + add;
    g_off[i] = o;
    g_key[o] = ((unsigned long long)i << 44) | ((unsigned long long)i << 22); // diag
    g_cur[i] = o + 1u;
    if (i == NN - 1) g_off[NN] = o + g_cnt[i] + 1u;   // == NBLK
}

// Fill edge blocks: cat1 under row[e] targeting col[e]; cat2 under col[e] targeting row[e].
__global__ void k_fill(const int* __restrict__ ei) {
    int e = blockIdx.x * blockDim.x + threadIdx.x;
    if (e >= NE) return;
    unsigned r = (unsigned)ei[e];
    unsigned c = (unsigned)ei[TWO_E + e];
    unsigned s1 = atomicAdd(&g_cur[r], 1u);
    g_key[s1] = ((unsigned long long)r << 44) | ((unsigned long long)c << 22)
              | (1ull << 20) | (unsigned long long)e;
    unsigned s2 = atomicAdd(&g_cur[c], 1u);
    g_key[s2] = ((unsigned long long)c << 44) | ((unsigned long long)r << 22)
              | (2ull << 20) | (unsigned long long)e;
}

// Warp-per-node two-phase rank sort.
// Phase 1 (O(cnt^2/32), rank ONLY): ~4-5 SASS instrs per comparison.
// Phase 2 (O(cnt)): coalesced g_key writes from the sorted smem buffer +
// neighbor-scan run detection (runs of equal t are adjacent & almost always
// length 1, so the while loops fail immediately).
__global__ void k_sort() {
    unsigned gw = (blockIdx.x * blockDim.x + threadIdx.x) >> 5;
    int lane = threadIdx.x & 31;
    int wloc = (int)(threadIdx.x >> 5);
    __shared__ unsigned long long sIn[4][MAXL];
    __shared__ unsigned long long sOut[4][MAXL];
    if (gw >= NN) return;
    unsigned off = g_off[gw];
    int cnt = (int)(g_off[gw + 1] - off);

    if (cnt <= MAXL) {
        unsigned long long* bin  = sIn[wloc];
        unsigned long long* bout = sOut[wloc];
        for (int i = lane; i < cnt; i += 32) bin[i] = g_key[off + i];
        __syncwarp();
        // Phase 1: rank only (keys unique within node -> ranks are a permutation)
        for (int i = lane; i < cnt; i += 32) {
            unsigned long long x = bin[i];
            int rank = 0;
#pragma unroll 4
            for (int q = 0; q < cnt; q++) rank += (bin[q] < x);
            bout[rank] = x;
        }
        __syncwarp();
        // Phase 2: coalesced writeback + local run detection
        for (int i = lane; i < cnt; i += 32) {
            unsigned long long x = bout[i];
            g_key[off + i] = x;
            unsigned long long tx = x >> 22;
            int lo = i, hi = i;
            while (lo > 0 && (bout[lo - 1] >> 22) == tx) lo--;
            while (hi + 1 < cnt && (bout[hi + 1] >> 22) == tx) hi++;
            g_run[off + i] = ((unsigned)(hi - lo + 1) << 16) | (unsigned)(i - lo);
        }
    } else if (lane == 0) {
        // safety fallback; never triggers for this dataset
        for (int i = 1; i < cnt; i++) {
            unsigned long long x = g_key[off + i];
            int j = i - 1;
            while (j >= 0 && g_key[off + j] > x) { g_key[off + j + 1] = g_key[off + j]; j--; }
            g_key[off + j + 1] = x;
        }
        int i = 0;
        while (i < cnt) {
            unsigned long long t = g_key[off + i] >> 22;
            int j = i + 1;
            while (j < cnt && (g_key[off + j] >> 22) == t) j++;
            unsigned m = (unsigned)(j - i);
            for (int q = i; q < j; q++)
                g_run[off + q] = (m << 16) | (unsigned)(q - i);
            i = j;
        }
    }
}

// Emit: one thread per (block slot, a). Within a (node, a) output row the
// entry order is (t, b, cat, e): blocks with distinct t emit 4 contiguous
// entries; runs of m>1 blocks sharing t emit b-interleaved (stride m).
__global__ void k_emit(const float* __restrict__ maps,
                       float* __restrict__ out) {
    unsigned tid = blockIdx.x * blockDim.x + threadIdx.x;
    if (tid >= (unsigned)NBLK * 4u) return;
    unsigned s = tid >> 2;
    int a = (int)(tid & 3u);

    unsigned long long key = g_key[s];
    unsigned node = (unsigned)(key >> 44);
    unsigned t    = (unsigned)(key >> 22) & 0x3FFFFFu;
    int      cat  = (int)((key >> 20) & 3ull);
    unsigned e    = (unsigned)(key & 0xFFFFFull);

    unsigned off = g_off[node];
    unsigned cnt = g_off[node + 1] - off;
    unsigned k   = s - off;

    float4 v;
    if (cat == 0) {
        const float* tri = g_diag + (size_t)node * 12;
        float vb[4];
#pragma unroll
        for (int b = 0; b < 4; b++) {
            int i2 = a < b ? a : b;
            int j2 = a < b ? b : a;
            vb[b] = tri[i2*4 + j2 - ((i2*(i2+1)) >> 1)];
        }
        v = make_float4(vb[0], vb[1], vb[2], vb[3]);
    } else {
        const float* L = maps + (size_t)e * 16;
        const float* R = maps + (size_t)(NE + e) * 16;
        // cat1: v[b] = -sum_r L[r][a] * R[r][b]   (triu[a][b])
        // cat2: v[b] = -sum_r R[r][a] * L[r][b]   (triu[b][a])
        const float* sel = (cat == 1) ? L : R;
        const float* mat = (cat == 1) ? R : L;
        float s0 = sel[0*4 + a], s1 = sel[1*4 + a], s2 = sel[2*4 + a], s3 = sel[3*4 + a];
        const float4* m4 = reinterpret_cast<const float4*>(mat);
        float4 q0 = m4[0], q1 = m4[1], q2 = m4[2], q3 = m4[3];
        v.x = -(s0*q0.x + s1*q1.x + s2*q2.x + s3*q3.x);
        v.y = -(s0*q0.y + s1*q1.y + s2*q2.y + s3*q3.y);
        v.z = -(s0*q0.z + s1*q1.z + s2*q2.z + s3*q3.z);
        v.w = -(s0*q0.w + s1*q1.w + s2*q2.w + s3*q3.w);
    }

    unsigned run = g_run[s];
    unsigned m = run >> 16;
    unsigned j = run & 0xFFFFu;
    float rowv = (float)(node * 4 + a);
    float cb   = (float)(t * 4u);

    if (m == 1u) {
        // fast path: 4 contiguous entries, float4 stores
        unsigned g = off * 16u + (unsigned)a * cnt * 4u + k * 4u;   // 4-aligned
        float4* rows = reinterpret_cast<float4*>(out);
        float4* cols = reinterpret_cast<float4*>(out + (size_t)NENT);
        float4* vals = reinterpret_cast<float4*>(out + (size_t)2 * NENT);
        rows[g >> 2] = make_float4(rowv, rowv, rowv, rowv);
        cols[g >> 2] = make_float4(cb, cb + 1.0f, cb + 2.0f, cb + 3.0f);
        vals[g >> 2] = v;
    } else {
        // rare path: blocks sharing t interleave by b with stride m
        unsigned k0 = k - j;
        size_t base = (size_t)off * 16u + (size_t)a * cnt * 4u + (size_t)k0 * 4u + j;
        float* rows = out;
        float* cols = out + (size_t)NENT;
        float* vals = out + (size_t)2 * NENT;
        float vb[4] = {v.x, v.y, v.z, v.w};
#pragma unroll
        for (unsigned b = 0; b < 4; b++) {
            size_t pos = base + (size_t)b * m;
            rows[pos] = rowv;
            cols[pos] = cb + (float)b;
            vals[pos] = vb[b];
        }
    }
}

extern "C" void kernel_launch(void* const* d_in, const int* in_sizes, int n_in,
                              void* d_out, int out_size) {
    const float* maps = (const float*)d_in[0];
    const int*   ei   = (const int*)d_in[1];
    float*       out  = (float*)d_out;

    void *p_diag, *p_cnt;
    cudaGetSymbolAddress(&p_diag, g_diag);
    cudaGetSymbolAddress(&p_cnt, g_cnt);
    cudaMemsetAsync(p_diag, 0, sizeof(float) * NN * 12);
    cudaMemsetAsync(p_cnt, 0, sizeof(unsigned) * NN);

    k_diag_count<<<(TWO_E + 255)/256, 256>>>(maps, ei);
    k_scan1     <<<NSB, SCAN_B>>>();
    k_scan3     <<<(NN + 255)/256, 256>>>();
    k_fill      <<<(NE + 255)/256, 256>>>(ei);
    k_sort      <<<(NN*32 + 127)/128, 128>>>();
    {
        unsigned total = (unsigned)NBLK * 4u;
        k_emit  <<<(total + 255)/256, 256>>>(maps, out);
    }
    (void)in_sizes; (void)n_in; (void)out_size;
}

// round 14
// speedup vs baseline: 1.2157x; 1.0002x over previous
#include <cuda_runtime.h>

// Problem constants (fixed by setup_inputs)
#define TWO_E   1600000
#define NE      800000
#define NN      50000
#define NBLK    (NN + 2*NE)          // 1,650,000 blocks total
#define NENT    (NBLK*16)            // 26,400,000 COO entries
#define SCAN_B  1024
#define NSB     ((NN + SCAN_B - 1)/SCAN_B)   // 49
#define MAXL    128                  // per-node capacity (Poisson(32): never exceeded)

// Key layout (u64):  node<<44 | t<<22 | cat<<20 | e
// g_diag: packed upper triangle of symmetric M^T M per node, 12 floats:
// [c00,c01,c02,c03, c11,c12,c13,c22, c23,c33, pad,pad]; tri(a<=b) = a*4+b-a*(a+1)/2

__device__ float                  g_diag[NN*12];
__device__ unsigned int           g_cnt[NN];
__device__ unsigned int           g_off[NN+1];
__device__ unsigned int           g_cur[NN];
__device__ unsigned long long     g_key[NBLK];
__device__ unsigned int           g_run[NBLK];       // (run_len<<16)|idx_in_run
__device__ unsigned int           g_partial[NSB];    // raw per-block sums

// Light counting pass: per edge e<E, nodes row[e] and col[e] each gain one
// edge block. Reads only the index arrays.
__global__ void k_count(const int* __restrict__ ei) {
    int e = blockIdx.x * blockDim.x + threadIdx.x;
    if (e >= NE) return;
    atomicAdd(&g_cnt[ei[e]], 1u);
    atomicAdd(&g_cnt[ei[TWO_E + e]], 1u);
}

// Scan phase 1: per-block exclusive scan over (cnt[i] + 1); raw block sums -> g_partial
__global__ void k_scan1() {
    __shared__ unsigned sh[SCAN_B];
    unsigned i = blockIdx.x * SCAN_B + threadIdx.x;
    unsigned v = (i < NN) ? (g_cnt[i] + 1u) : 0u;
    sh[threadIdx.x] = v;
    __syncthreads();
    for (int d = 1; d < SCAN_B; d <<= 1) {
        unsigned t = (threadIdx.x >= (unsigned)d) ? sh[threadIdx.x - d] : 0u;
        __syncthreads();
        sh[threadIdx.x] += t;
        __syncthreads();
    }
    if (i < NN) g_off[i] = sh[threadIdx.x] - v;     // exclusive within block
    if (threadIdx.x == SCAN_B - 1) g_partial[blockIdx.x] = sh[SCAN_B - 1];
}

// Scan phase 3 (full grid): each thread sums preceding block partials inline
// (<=48 L1-broadcast loads). Also seeds diag key + fill cursor; last thread
// writes the grand total.
__global__ void k_scan3() {
    unsigned i = blockIdx.x * blockDim.x + threadIdx.x;
    if (i >= NN) return;
    unsigned nb = i >> 10;
    unsigned add = 0;
    for (unsigned b = 0; b < nb; b++) add += g_partial[b];
    unsigned o = g_off[i] + add;
    g_off[i] = o;
    g_key[o] = ((unsigned long long)i << 44) | ((unsigned long long)i << 22); // diag
    g_cur[i] = o + 1u;
    if (i == NN - 1) g_off[NN] = o + g_cnt[i] + 1u;   // == NBLK
}

// Helper: packed-triangle M^T M reductions for one 4x4 map into g_diag[node].
__device__ __forceinline__ void diag_reduce(const float4* M4, unsigned node) {
    float4 r0 = M4[0], r1 = M4[1], r2 = M4[2], r3 = M4[3];
    float m[4][4] = {
        {r0.x, r0.y, r0.z, r0.w},
        {r1.x, r1.y, r1.z, r1.w},
        {r2.x, r2.y, r2.z, r2.w},
        {r3.x, r3.y, r3.z, r3.w}
    };
    float* tri = g_diag + (size_t)node * 12;
    float c00 = m[0][0]*m[0][0] + m[1][0]*m[1][0] + m[2][0]*m[2][0] + m[3][0]*m[3][0];
    float c01 = m[0][0]*m[0][1] + m[1][0]*m[1][1] + m[2][0]*m[2][1] + m[3][0]*m[3][1];
    float c02 = m[0][0]*m[0][2] + m[1][0]*m[1][2] + m[2][0]*m[2][2] + m[3][0]*m[3][2];
    float c03 = m[0][0]*m[0][3] + m[1][0]*m[1][3] + m[2][0]*m[2][3] + m[3][0]*m[3][3];
    float c11 = m[0][1]*m[0][1] + m[1][1]*m[1][1] + m[2][1]*m[2][1] + m[3][1]*m[3][1];
    float c12 = m[0][1]*m[0][2] + m[1][1]*m[1][2] + m[2][1]*m[2][2] + m[3][1]*m[3][2];
    float c13 = m[0][1]*m[0][3] + m[1][1]*m[1][3] + m[2][1]*m[2][3] + m[3][1]*m[3][3];
    float c22 = m[0][2]*m[0][2] + m[1][2]*m[1][2] + m[2][2]*m[2][2] + m[3][2]*m[3][2];
    float c23 = m[0][2]*m[0][3] + m[1][2]*m[1][3] + m[2][2]*m[2][3] + m[3][2]*m[3][3];
    float c33 = m[0][3]*m[0][3] + m[1][3]*m[1][3] + m[2][3]*m[2][3] + m[3][3]*m[3][3];
    asm volatile("red.global.add.v4.f32 [%0], {%1, %2, %3, %4};"
                 :: "l"(tri + 0), "f"(c00), "f"(c01), "f"(c02), "f"(c03) : "memory");
    asm volatile("red.global.add.v4.f32 [%0], {%1, %2, %3, %4};"
                 :: "l"(tri + 4), "f"(c11), "f"(c12), "f"(c13), "f"(c22) : "memory");
    asm volatile("red.global.add.v2.f32 [%0], {%1, %2};"
                 :: "l"(tri + 8), "f"(c23), "f"(c33) : "memory");
}

// Fused fill + diag: per edge e, writes both edge-block keys (cursor atomics)
// AND computes the two M^T M diag contributions (rows e and E+e of maps,
// scattered to ei[e] and ei[E+e]). The diag work hides inside the cursor
// atomics' latency (fill was at 3% issue, 84% occ).
__global__ void k_fill_diag(const float* __restrict__ maps,
                            const int*   __restrict__ ei) {
    int e = blockIdx.x * blockDim.x + threadIdx.x;
    if (e >= NE) return;
    unsigned r  = (unsigned)ei[e];              // edge_index[0][e]
    unsigned rr = (unsigned)ei[NE + e];         // edge_index[0][E+e]
    unsigned c  = (unsigned)ei[TWO_E + e];      // edge_index[1][e]

    // kick off cursor atomics early (long latency)
    unsigned s1 = atomicAdd(&g_cur[r], 1u);
    unsigned s2 = atomicAdd(&g_cur[c], 1u);

    // diag contributions for maps rows e (-> node r) and E+e (-> node rr)
    diag_reduce(reinterpret_cast<const float4*>(maps + (size_t)e * 16), r);
    diag_reduce(reinterpret_cast<const float4*>(maps + (size_t)(NE + e) * 16), rr);

    g_key[s1] = ((unsigned long long)r << 44) | ((unsigned long long)c << 22)
              | (1ull << 20) | (unsigned long long)e;
    g_key[s2] = ((unsigned long long)c << 44) | ((unsigned long long)r << 22)
              | (2ull << 20) | (unsigned long long)e;
}

// Warp-per-node two-phase rank sort.
// Phase 1 (O(cnt^2/32), rank ONLY). Phase 2 (O(cnt)): coalesced g_key writes
// + neighbor-scan run detection.
__global__ void k_sort() {
    unsigned gw = (blockIdx.x * blockDim.x + threadIdx.x) >> 5;
    int lane = threadIdx.x & 31;
    int wloc = (int)(threadIdx.x >> 5);
    __shared__ unsigned long long sIn[4][MAXL];
    __shared__ unsigned long long sOut[4][MAXL];
    if (gw >= NN) return;
    unsigned off = g_off[gw];
    int cnt = (int)(g_off[gw + 1] - off);

    if (cnt <= MAXL) {
        unsigned long long* bin  = sIn[wloc];
        unsigned long long* bout = sOut[wloc];
        for (int i = lane; i < cnt; i += 32) bin[i] = g_key[off + i];
        __syncwarp();
        for (int i = lane; i < cnt; i += 32) {
            unsigned long long x = bin[i];
            int rank = 0;
#pragma unroll 4
            for (int q = 0; q < cnt; q++) rank += (bin[q] < x);
            bout[rank] = x;
        }
        __syncwarp();
        for (int i = lane; i < cnt; i += 32) {
            unsigned long long x = bout[i];
            g_key[off + i] = x;
            unsigned long long tx = x >> 22;
            int lo = i, hi = i;
            while (lo > 0 && (bout[lo - 1] >> 22) == tx) lo--;
            while (hi + 1 < cnt && (bout[hi + 1] >> 22) == tx) hi++;
            g_run[off + i] = ((unsigned)(hi - lo + 1) << 16) | (unsigned)(i - lo);
        }
    } else if (lane == 0) {
        // safety fallback; never triggers for this dataset
        for (int i = 1; i < cnt; i++) {
            unsigned long long x = g_key[off + i];
            int j = i - 1;
            while (j >= 0 && g_key[off + j] > x) { g_key[off + j + 1] = g_key[off + j]; j--; }
            g_key[off + j + 1] = x;
        }
        int i = 0;
        while (i < cnt) {
            unsigned long long t = g_key[off + i] >> 22;
            int j = i + 1;
            while (j < cnt && (g_key[off + j] >> 22) == t) j++;
            unsigned m = (unsigned)(j - i);
            for (int q = i; q < j; q++)
                g_run[off + q] = (m << 16) | (unsigned)(q - i);
            i = j;
        }
    }
}

// Emit: one thread per (block slot, a). Within a (node, a) output row the
// entry order is (t, b, cat, e): blocks with distinct t emit 4 contiguous
// entries; runs of m>1 blocks sharing t emit b-interleaved (stride m).
__global__ void k_emit(const float* __restrict__ maps,
                       float* __restrict__ out) {
    unsigned tid = blockIdx.x * blockDim.x + threadIdx.x;
    if (tid >= (unsigned)NBLK * 4u) return;
    unsigned s = tid >> 2;
    int a = (int)(tid & 3u);

    unsigned long long key = g_key[s];
    unsigned node = (unsigned)(key >> 44);
    unsigned t    = (unsigned)(key >> 22) & 0x3FFFFFu;
    int      cat  = (int)((key >> 20) & 3ull);
    unsigned e    = (unsigned)(key & 0xFFFFFull);

    unsigned off = g_off[node];
    unsigned cnt = g_off[node + 1] - off;
    unsigned k   = s - off;

    float4 v;
    if (cat == 0) {
        const float* tri = g_diag + (size_t)node * 12;
        float vb[4];
#pragma unroll
        for (int b = 0; b < 4; b++) {
            int i2 = a < b ? a : b;
            int j2 = a < b ? b : a;
            vb[b] = tri[i2*4 + j2 - ((i2*(i2+1)) >> 1)];
        }
        v = make_float4(vb[0], vb[1], vb[2], vb[3]);
    } else {
        const float* L = maps + (size_t)e * 16;
        const float* R = maps + (size_t)(NE + e) * 16;
        // cat1: v[b] = -sum_r L[r][a] * R[r][b]   (triu[a][b])
        // cat2: v[b] = -sum_r R[r][a] * L[r][b]   (triu[b][a])
        const float* sel = (cat == 1) ? L : R;
        const float* mat = (cat == 1) ? R : L;
        float s0 = sel[0*4 + a], s1 = sel[1*4 + a], s2 = sel[2*4 + a], s3 = sel[3*4 + a];
        const float4* m4 = reinterpret_cast<const float4*>(mat);
        float4 q0 = m4[0], q1 = m4[1], q2 = m4[2], q3 = m4[3];
        v.x = -(s0*q0.x + s1*q1.x + s2*q2.x + s3*q3.x);
        v.y = -(s0*q0.y + s1*q1.y + s2*q2.y + s3*q3.y);
        v.z = -(s0*q0.z + s1*q1.z + s2*q2.z + s3*q3.z);
        v.w = -(s0*q0.w + s1*q1.w + s2*q2.w + s3*q3.w);
    }

    unsigned run = g_run[s];
    unsigned m = run >> 16;
    unsigned j = run & 0xFFFFu;
    float rowv = (float)(node * 4 + a);
    float cb   = (float)(t * 4u);

    if (m == 1u) {
        // fast path: 4 contiguous entries, float4 stores
        unsigned g = off * 16u + (unsigned)a * cnt * 4u + k * 4u;   // 4-aligned
        float4* rows = reinterpret_cast<float4*>(out);
        float4* cols = reinterpret_cast<float4*>(out + (size_t)NENT);
        float4* vals = reinterpret_cast<float4*>(out + (size_t)2 * NENT);
        rows[g >> 2] = make_float4(rowv, rowv, rowv, rowv);
        cols[g >> 2] = make_float4(cb, cb + 1.0f, cb + 2.0f, cb + 3.0f);
        vals[g >> 2] = v;
    } else {
        // rare path: blocks sharing t interleave by b with stride m
        unsigned k0 = k - j;
        size_t base = (size_t)off * 16u + (size_t)a * cnt * 4u + (size_t)k0 * 4u + j;
        float* rows = out;
        float* cols = out + (size_t)NENT;
        float* vals = out + (size_t)2 * NENT;
        float vb[4] = {v.x, v.y, v.z, v.w};
#pragma unroll
        for (unsigned b = 0; b < 4; b++) {
            size_t pos = base + (size_t)b * m;
            rows[pos] = rowv;
            cols[pos] = cb + (float)b;
            vals[pos] = vb[b];
        }
    }
}

extern "C" void kernel_launch(void* const* d_in, const int* in_sizes, int n_in,
                              void* d_out, int out_size) {
    const float* maps = (const float*)d_in[0];
    const int*   ei   = (const int*)d_in[1];
    float*       out  = (float*)d_out;

    void *p_diag, *p_cnt;
    cudaGetSymbolAddress(&p_diag, g_diag);
    cudaGetSymbolAddress(&p_cnt, g_cnt);
    cudaMemsetAsync(p_diag, 0, sizeof(float) * NN * 12);
    cudaMemsetAsync(p_cnt, 0, sizeof(unsigned) * NN);

    k_count     <<<(NE + 255)/256, 256>>>(ei);
    k_scan1     <<<NSB, SCAN_B>>>();
    k_scan3     <<<(NN + 255)/256, 256>>>();
    k_fill_diag <<<(NE + 255)/256, 256>>>(maps, ei);
    k_sort      <<<(NN*32 + 127)/128, 128>>>();
    {
        unsigned total = (unsigned)NBLK * 4u;
        k_emit  <<<(total + 255)/256, 256>>>(maps, out);
    }
    (void)in_sizes; (void)n_in; (void)out_size;
}

// round 16
// speedup vs baseline: 1.2570x; 1.0339x over previous
#include <cuda_runtime.h>

// Problem constants (fixed by setup_inputs)
#define TWO_E   1600000
#define NE      800000
#define NN      50000
#define NBLK    (NN + 2*NE)          // 1,650,000 blocks total
#define NENT    (NBLK*16)            // 26,400,000 COO entries
#define SCAN_B  1024
#define NSB     ((NN + SCAN_B - 1)/SCAN_B)   // 49
#define MAXL    128                  // per-node capacity (Poisson(32): never exceeded)

// Key layout (u64):  node<<44 | t<<22 | cat<<20 | e
// g_diag: packed upper triangle of symmetric M^T M per node, 12 floats.
// g_tile: per-edge negated product tile  -L^T R , 16 floats [a*4+b].

__device__ float                  g_diag[NN*12];
__device__ float                  g_tile[(size_t)NE*16];   // 51.2 MB
__device__ unsigned int           g_cnt[NN];
__device__ unsigned int           g_off[NN+1];
__device__ unsigned int           g_cur[NN];
__device__ unsigned long long     g_key[NBLK];
__device__ unsigned int           g_run[NBLK];       // (run_len<<16)|idx_in_run
__device__ unsigned int           g_partial[NSB];    // raw per-block sums

// Light counting pass: per edge e<E, nodes row[e] and col[e] each gain one
// edge block. Reads only the index arrays.
__global__ void k_count(const int* __restrict__ ei) {
    int e = blockIdx.x * blockDim.x + threadIdx.x;
    if (e >= NE) return;
    atomicAdd(&g_cnt[ei[e]], 1u);
    atomicAdd(&g_cnt[ei[TWO_E + e]], 1u);
}

// Scan phase 1: per-block exclusive scan over (cnt[i] + 1)
__global__ void k_scan1() {
    __shared__ unsigned sh[SCAN_B];
    unsigned i = blockIdx.x * SCAN_B + threadIdx.x;
    unsigned v = (i < NN) ? (g_cnt[i] + 1u) : 0u;
    sh[threadIdx.x] = v;
    __syncthreads();
    for (int d = 1; d < SCAN_B; d <<= 1) {
        unsigned t = (threadIdx.x >= (unsigned)d) ? sh[threadIdx.x - d] : 0u;
        __syncthreads();
        sh[threadIdx.x] += t;
        __syncthreads();
    }
    if (i < NN) g_off[i] = sh[threadIdx.x] - v;
    if (threadIdx.x == SCAN_B - 1) g_partial[blockIdx.x] = sh[SCAN_B - 1];
}

// Scan phase 3: inline partial accumulation + diag key/cursor seeding.
__global__ void k_scan3() {
    unsigned i = blockIdx.x * blockDim.x + threadIdx.x;
    if (i >= NN) return;
    unsigned nb = i >> 10;
    unsigned add = 0;
    for (unsigned b = 0; b < nb; b++) add += g_partial[b];
    unsigned o = g_off[i] + add;
    g_off[i] = o;
    g_key[o] = ((unsigned long long)i << 44) | ((unsigned long long)i << 22); // diag
    g_cur[i] = o + 1u;
    if (i == NN - 1) g_off[NN] = o + g_cnt[i] + 1u;   // == NBLK
}

// Packed-triangle M^T M reductions for one 4x4 map into g_diag[node].
__device__ __forceinline__ void diag_reduce(float4 r0, float4 r1, float4 r2, float4 r3,
                                            unsigned node) {
    float m[4][4] = {
        {r0.x, r0.y, r0.z, r0.w},
        {r1.x, r1.y, r1.z, r1.w},
        {r2.x, r2.y, r2.z, r2.w},
        {r3.x, r3.y, r3.z, r3.w}
    };
    float* tri = g_diag + (size_t)node * 12;
    float c00 = m[0][0]*m[0][0] + m[1][0]*m[1][0] + m[2][0]*m[2][0] + m[3][0]*m[3][0];
    float c01 = m[0][0]*m[0][1] + m[1][0]*m[1][1] + m[2][0]*m[2][1] + m[3][0]*m[3][1];
    float c02 = m[0][0]*m[0][2] + m[1][0]*m[1][2] + m[2][0]*m[2][2] + m[3][0]*m[3][2];
    float c03 = m[0][0]*m[0][3] + m[1][0]*m[1][3] + m[2][0]*m[2][3] + m[3][0]*m[3][3];
    float c11 = m[0][1]*m[0][1] + m[1][1]*m[1][1] + m[2][1]*m[2][1] + m[3][1]*m[3][1];
    float c12 = m[0][1]*m[0][2] + m[1][1]*m[1][2] + m[2][1]*m[2][2] + m[3][1]*m[3][2];
    float c13 = m[0][1]*m[0][3] + m[1][1]*m[1][3] + m[2][1]*m[2][3] + m[3][1]*m[3][3];
    float c22 = m[0][2]*m[0][2] + m[1][2]*m[1][2] + m[2][2]*m[2][2] + m[3][2]*m[3][2];
    float c23 = m[0][2]*m[0][3] + m[1][2]*m[1][3] + m[2][2]*m[2][3] + m[3][2]*m[3][3];
    float c33 = m[0][3]*m[0][3] + m[1][3]*m[1][3] + m[2][3]*m[2][3] + m[3][3]*m[3][3];
    asm volatile("red.global.add.v4.f32 [%0], {%1, %2, %3, %4};"
                 :: "l"(tri + 0), "f"(c00), "f"(c01), "f"(c02), "f"(c03) : "memory");
    asm volatile("red.global.add.v4.f32 [%0], {%1, %2, %3, %4};"
                 :: "l"(tri + 4), "f"(c11), "f"(c12), "f"(c13), "f"(c22) : "memory");
    asm volatile("red.global.add.v2.f32 [%0], {%1, %2};"
                 :: "l"(tri + 8), "f"(c23), "f"(c33) : "memory");
}

// Fused fill + diag + tile: per edge e, writes both edge-block keys (cursor
// atomics), both M^T M diag contributions, AND the negated product tile
// -L^T R (64B coalesced store) consumed by emit.
__global__ void k_fill_diag(const float* __restrict__ maps,
                            const int*   __restrict__ ei) {
    int e = blockIdx.x * blockDim.x + threadIdx.x;
    if (e >= NE) return;
    unsigned r  = (unsigned)ei[e];              // edge_index[0][e]
    unsigned rr = (unsigned)ei[NE + e];         // edge_index[0][E+e]
    unsigned c  = (unsigned)ei[TWO_E + e];      // edge_index[1][e]

    // kick off cursor atomics early (long latency)
    unsigned s1 = atomicAdd(&g_cur[r], 1u);
    unsigned s2 = atomicAdd(&g_cur[c], 1u);

    const float4* L4 = reinterpret_cast<const float4*>(maps + (size_t)e * 16);
    const float4* R4 = reinterpret_cast<const float4*>(maps + (size_t)(NE + e) * 16);
    float4 l0 = L4[0], l1 = L4[1], l2 = L4[2], l3 = L4[3];
    float4 q0 = R4[0], q1 = R4[1], q2 = R4[2], q3 = R4[3];

    diag_reduce(l0, l1, l2, l3, r);
    diag_reduce(q0, q1, q2, q3, rr);

    // tile[a][b] = -(sum_k L[k][a] * R[k][b])
    float la[4][4] = {{l0.x,l0.y,l0.z,l0.w},{l1.x,l1.y,l1.z,l1.w},
                      {l2.x,l2.y,l2.z,l2.w},{l3.x,l3.y,l3.z,l3.w}};
    float ra[4][4] = {{q0.x,q0.y,q0.z,q0.w},{q1.x,q1.y,q1.z,q1.w},
                      {q2.x,q2.y,q2.z,q2.w},{q3.x,q3.y,q3.z,q3.w}};
    float4* tdst = reinterpret_cast<float4*>(g_tile + (size_t)e * 16);
#pragma unroll
    for (int a = 0; a < 4; a++) {
        float4 p;
        p.x = -(la[0][a]*ra[0][0] + la[1][a]*ra[1][0] + la[2][a]*ra[2][0] + la[3][a]*ra[3][0]);
        p.y = -(la[0][a]*ra[0][1] + la[1][a]*ra[1][1] + la[2][a]*ra[2][1] + la[3][a]*ra[3][1]);
        p.z = -(la[0][a]*ra[0][2] + la[1][a]*ra[1][2] + la[2][a]*ra[2][2] + la[3][a]*ra[3][2]);
        p.w = -(la[0][a]*ra[0][3] + la[1][a]*ra[1][3] + la[2][a]*ra[2][3] + la[3][a]*ra[3][3]);
        tdst[a] = p;
    }

    g_key[s1] = ((unsigned long long)r << 44) | ((unsigned long long)c << 22)
              | (1ull << 20) | (unsigned long long)e;
    g_key[s2] = ((unsigned long long)c << 44) | ((unsigned long long)r << 22)
              | (2ull << 20) | (unsigned long long)e;
}

// Warp-per-node two-phase rank sort (rank-only O(cnt^2/32) + O(cnt) finish).
__global__ void k_sort() {
    unsigned gw = (blockIdx.x * blockDim.x + threadIdx.x) >> 5;
    int lane = threadIdx.x & 31;
    int wloc = (int)(threadIdx.x >> 5);
    __shared__ unsigned long long sIn[4][MAXL];
    __shared__ unsigned long long sOut[4][MAXL];
    if (gw >= NN) return;
    unsigned off = g_off[gw];
    int cnt = (int)(g_off[gw + 1] - off);

    if (cnt <= MAXL) {
        unsigned long long* bin  = sIn[wloc];
        unsigned long long* bout = sOut[wloc];
        for (int i = lane; i < cnt; i += 32) bin[i] = g_key[off + i];
        __syncwarp();
        for (int i = lane; i < cnt; i += 32) {
            unsigned long long x = bin[i];
            int rank = 0;
#pragma unroll 4
            for (int q = 0; q < cnt; q++) rank += (bin[q] < x);
            bout[rank] = x;
        }
        __syncwarp();
        for (int i = lane; i < cnt; i += 32) {
            unsigned long long x = bout[i];
            g_key[off + i] = x;
            unsigned long long tx = x >> 22;
            int lo = i, hi = i;
            while (lo > 0 && (bout[lo - 1] >> 22) == tx) lo--;
            while (hi + 1 < cnt && (bout[hi + 1] >> 22) == tx) hi++;
            g_run[off + i] = ((unsigned)(hi - lo + 1) << 16) | (unsigned)(i - lo);
        }
    } else if (lane == 0) {
        // safety fallback; never triggers for this dataset
        for (int i = 1; i < cnt; i++) {
            unsigned long long x = g_key[off + i];
            int j = i - 1;
            while (j >= 0 && g_key[off + j] > x) { g_key[off + j + 1] = g_key[off + j]; j--; }
            g_key[off + j + 1] = x;
        }
        int i = 0;
        while (i < cnt) {
            unsigned long long t = g_key[off + i] >> 22;
            int j = i + 1;
            while (j < cnt && (g_key[off + j] >> 22) == t) j++;
            unsigned m = (unsigned)(j - i);
            for (int q = i; q < j; q++)
                g_run[off + q] = (m << 16) | (unsigned)(q - i);
            i = j;
        }
    }
}

// Emit: one thread per (block slot, a). Edge values come precomputed from
// g_tile: cat1 thread a reads tile row a (one float4); cat2 thread a reads
// tile column a (4 scalars). The 4 threads of a block collectively touch
// exactly the 64B tile.
__global__ void k_emit(float* __restrict__ out) {
    unsigned tid = blockIdx.x * blockDim.x + threadIdx.x;
    if (tid >= (unsigned)NBLK * 4u) return;
    unsigned s = tid >> 2;
    int a = (int)(tid & 3u);

    unsigned long long key = g_key[s];
    unsigned node = (unsigned)(key >> 44);
    unsigned t    = (unsigned)(key >> 22) & 0x3FFFFFu;
    int      cat  = (int)((key >> 20) & 3ull);
    unsigned e    = (unsigned)(key & 0xFFFFFull);

    unsigned off = g_off[node];
    unsigned cnt = g_off[node + 1] - off;
    unsigned k   = s - off;

    float4 v;
    if (cat == 0) {
        const float* tri = g_diag + (size_t)node * 12;
        float vb[4];
#pragma unroll
        for (int b = 0; b < 4; b++) {
            int i2 = a < b ? a : b;
            int j2 = a < b ? b : a;
            vb[b] = tri[i2*4 + j2 - ((i2*(i2+1)) >> 1)];
        }
        v = make_float4(vb[0], vb[1], vb[2], vb[3]);
    } else if (cat == 1) {
        v = *reinterpret_cast<const float4*>(g_tile + (size_t)e * 16 + a * 4);
    } else {
        const float* tp = g_tile + (size_t)e * 16 + a;   // column a, stride 4
        v = make_float4(tp[0], tp[4], tp[8], tp[12]);
    }

    unsigned run = g_run[s];
    unsigned m = run >> 16;
    unsigned j = run & 0xFFFFu;
    float rowv = (float)(node * 4 + a);
    float cb   = (float)(t * 4u);

    if (m == 1u) {
        // fast path: 4 contiguous entries, float4 stores
        unsigned g = off * 16u + (unsigned)a * cnt * 4u + k * 4u;   // 4-aligned
        float4* rows = reinterpret_cast<float4*>(out);
        float4* cols = reinterpret_cast<float4*>(out + (size_t)NENT);
        float4* vals = reinterpret_cast<float4*>(out + (size_t)2 * NENT);
        rows[g >> 2] = make_float4(rowv, rowv, rowv, rowv);
        cols[g >> 2] = make_float4(cb, cb + 1.0f, cb + 2.0f, cb + 3.0f);
        vals[g >> 2] = v;
    } else {
        // rare path: blocks sharing t interleave by b with stride m
        unsigned k0 = k - j;
        size_t base = (size_t)off * 16u + (size_t)a * cnt * 4u + (size_t)k0 * 4u + j;
        float* rows = out;
        float* cols = out + (size_t)NENT;
        float* vals = out + (size_t)2 * NENT;
        float vb[4] = {v.x, v.y, v.z, v.w};
#pragma unroll
        for (unsigned b = 0; b < 4; b++) {
            size_t pos = base + (size_t)b * m;
            rows[pos] = rowv;
            cols[pos] = cb + (float)b;
            vals[pos] = vb[b];
        }
    }
}

extern "C" void kernel_launch(void* const* d_in, const int* in_sizes, int n_in,
                              void* d_out, int out_size) {
    const float* maps = (const float*)d_in[0];
    const int*   ei   = (const int*)d_in[1];
    float*       out  = (float*)d_out;

    void *p_diag, *p_cnt;
    cudaGetSymbolAddress(&p_diag, g_diag);
    cudaGetSymbolAddress(&p_cnt, g_cnt);
    cudaMemsetAsync(p_diag, 0, sizeof(float) * NN * 12);
    cudaMemsetAsync(p_cnt, 0, sizeof(unsigned) * NN);

    k_count     <<<(NE + 255)/256, 256>>>(ei);
    k_scan1     <<<NSB, SCAN_B>>>();
    k_scan3     <<<(NN + 255)/256, 256>>>();
    k_fill_diag <<<(NE + 255)/256, 256>>>(maps, ei);
    k_sort      <<<(NN*32 + 127)/128, 128>>>();
    {
        unsigned total = (unsigned)NBLK * 4u;
        k_emit  <<<(total + 255)/256, 256>>>(out);
    }
    (void)in_sizes; (void)n_in; (void)out_size;
}

// round 17
// speedup vs baseline: 1.2659x; 1.0071x over previous
#include <cuda_runtime.h>

// Problem constants (fixed by setup_inputs)
#define TWO_E   1600000
#define NE      800000
#define NN      50000
#define NBLK    (NN + 2*NE)          // 1,650,000 blocks total
#define NENT    (NBLK*16)            // 26,400,000 COO entries
#define SCAN_B  1024
#define NSB     ((NN + SCAN_B - 1)/SCAN_B)   // 49
#define MAXL    128                  // per-node capacity (Poisson(32): never exceeded)

// Key layout (u64):  node<<44 | t<<22 | cat<<20 | e
// g_diag: packed upper triangle of symmetric M^T M per node, 12 floats.
// g_tile: per-edge negated product tile  -L^T R , 16 floats [a*4+b].

__device__ float                  g_diag[NN*12];
__device__ float                  g_tile[(size_t)NE*16];   // 51.2 MB
__device__ unsigned int           g_cnt[NN];
__device__ unsigned int           g_off[NN+1];
__device__ unsigned int           g_cur[NN];
__device__ unsigned long long     g_key[NBLK];
__device__ unsigned int           g_run[NBLK];       // (run_len<<16)|idx_in_run
__device__ unsigned int           g_partial[NSB];    // raw per-block sums

// Light counting pass: per edge e<E, nodes row[e] and col[e] each gain one
// edge block. Reads only the index arrays.
__global__ void k_count(const int* __restrict__ ei) {
    int e = blockIdx.x * blockDim.x + threadIdx.x;
    if (e >= NE) return;
    atomicAdd(&g_cnt[ei[e]], 1u);
    atomicAdd(&g_cnt[ei[TWO_E + e]], 1u);
}

// Scan phase 1: per-block exclusive scan over (cnt[i] + 1)
__global__ void k_scan1() {
    __shared__ unsigned sh[SCAN_B];
    unsigned i = blockIdx.x * SCAN_B + threadIdx.x;
    unsigned v = (i < NN) ? (g_cnt[i] + 1u) : 0u;
    sh[threadIdx.x] = v;
    __syncthreads();
    for (int d = 1; d < SCAN_B; d <<= 1) {
        unsigned t = (threadIdx.x >= (unsigned)d) ? sh[threadIdx.x - d] : 0u;
        __syncthreads();
        sh[threadIdx.x] += t;
        __syncthreads();
    }
    if (i < NN) g_off[i] = sh[threadIdx.x] - v;
    if (threadIdx.x == SCAN_B - 1) g_partial[blockIdx.x] = sh[SCAN_B - 1];
}

// Scan phase 3: inline partial accumulation + diag key/cursor seeding.
__global__ void k_scan3() {
    unsigned i = blockIdx.x * blockDim.x + threadIdx.x;
    if (i >= NN) return;
    unsigned nb = i >> 10;
    unsigned add = 0;
    for (unsigned b = 0; b < nb; b++) add += g_partial[b];
    unsigned o = g_off[i] + add;
    g_off[i] = o;
    g_key[o] = ((unsigned long long)i << 44) | ((unsigned long long)i << 22); // diag
    g_cur[i] = o + 1u;
    if (i == NN - 1) g_off[NN] = o + g_cnt[i] + 1u;   // == NBLK
}

// Packed-triangle M^T M reductions for one 4x4 map into g_diag[node].
__device__ __forceinline__ void diag_reduce(float4 r0, float4 r1, float4 r2, float4 r3,
                                            unsigned node) {
    float m[4][4] = {
        {r0.x, r0.y, r0.z, r0.w},
        {r1.x, r1.y, r1.z, r1.w},
        {r2.x, r2.y, r2.z, r2.w},
        {r3.x, r3.y, r3.z, r3.w}
    };
    float* tri = g_diag + (size_t)node * 12;
    float c00 = m[0][0]*m[0][0] + m[1][0]*m[1][0] + m[2][0]*m[2][0] + m[3][0]*m[3][0];
    float c01 = m[0][0]*m[0][1] + m[1][0]*m[1][1] + m[2][0]*m[2][1] + m[3][0]*m[3][1];
    float c02 = m[0][0]*m[0][2] + m[1][0]*m[1][2] + m[2][0]*m[2][2] + m[3][0]*m[3][2];
    float c03 = m[0][0]*m[0][3] + m[1][0]*m[1][3] + m[2][0]*m[2][3] + m[3][0]*m[3][3];
    float c11 = m[0][1]*m[0][1] + m[1][1]*m[1][1] + m[2][1]*m[2][1] + m[3][1]*m[3][1];
    float c12 = m[0][1]*m[0][2] + m[1][1]*m[1][2] + m[2][1]*m[2][2] + m[3][1]*m[3][2];
    float c13 = m[0][1]*m[0][3] + m[1][1]*m[1][3] + m[2][1]*m[2][3] + m[3][1]*m[3][3];
    float c22 = m[0][2]*m[0][2] + m[1][2]*m[1][2] + m[2][2]*m[2][2] + m[3][2]*m[3][2];
    float c23 = m[0][2]*m[0][3] + m[1][2]*m[1][3] + m[2][2]*m[2][3] + m[3][2]*m[3][3];
    float c33 = m[0][3]*m[0][3] + m[1][3]*m[1][3] + m[2][3]*m[2][3] + m[3][3]*m[3][3];
    asm volatile("red.global.add.v4.f32 [%0], {%1, %2, %3, %4};"
                 :: "l"(tri + 0), "f"(c00), "f"(c01), "f"(c02), "f"(c03) : "memory");
    asm volatile("red.global.add.v4.f32 [%0], {%1, %2, %3, %4};"
                 :: "l"(tri + 4), "f"(c11), "f"(c12), "f"(c13), "f"(c22) : "memory");
    asm volatile("red.global.add.v2.f32 [%0], {%1, %2};"
                 :: "l"(tri + 8), "f"(c23), "f"(c33) : "memory");
}

// Fused fill + diag + tile, TWO threads per edge. Even lane owns L (maps row
// e): diag -> node r, cursor atomic + cat1 key on r, tile rows 0-1. Odd lane
// owns R (maps row NE+e): diag -> node ei[NE+e], atomic + cat2 key on c,
// tile rows 2-3. Halves each thread's latency chain; partner-matrix loads
// dedup in L1/L2.
__global__ void __launch_bounds__(256) k_fill_diag(const float* __restrict__ maps,
                                                   const int*   __restrict__ ei) {
    unsigned tid = blockIdx.x * blockDim.x + threadIdx.x;
    unsigned e = tid >> 1;
    if (e >= NE) return;
    unsigned u = tid & 1u;

    unsigned r = (unsigned)ei[e];               // edge_index[0][e]
    unsigned c = (unsigned)ei[TWO_E + e];       // edge_index[1][e]
    unsigned dn = u ? (unsigned)ei[NE + e] : r; // diag target node
    unsigned sn = u ? c : r;                    // slot (cursor) node

    // cursor atomic early (long latency)
    unsigned slot = atomicAdd(&g_cur[sn], 1u);

    // own matrix
    const float4* own4 = reinterpret_cast<const float4*>(
        maps + (size_t)(u ? NE + e : e) * 16);
    float4 o0 = own4[0], o1 = own4[1], o2 = own4[2], o3 = own4[3];
    diag_reduce(o0, o1, o2, o3, dn);

    // partner matrix (same sectors as partner thread's own loads)
    const float4* p4 = reinterpret_cast<const float4*>(
        maps + (size_t)(u ? e : NE + e) * 16);
    float4 p0 = p4[0], p1 = p4[1], p2 = p4[2], p3 = p4[3];

    // L = maps[e], R = maps[NE+e]:  even has own=L, partner=R; odd swapped.
    float L[4][4], R[4][4];
    if (u == 0) {
        float lt[4][4] = {{o0.x,o0.y,o0.z,o0.w},{o1.x,o1.y,o1.z,o1.w},
                          {o2.x,o2.y,o2.z,o2.w},{o3.x,o3.y,o3.z,o3.w}};
        float rt[4][4] = {{p0.x,p0.y,p0.z,p0.w},{p1.x,p1.y,p1.z,p1.w},
                          {p2.x,p2.y,p2.z,p2.w},{p3.x,p3.y,p3.z,p3.w}};
#pragma unroll
        for (int i = 0; i < 4; i++)
#pragma unroll
            for (int j2 = 0; j2 < 4; j2++) { L[i][j2] = lt[i][j2]; R[i][j2] = rt[i][j2]; }
    } else {
        float lt[4][4] = {{p0.x,p0.y,p0.z,p0.w},{p1.x,p1.y,p1.z,p1.w},
                          {p2.x,p2.y,p2.z,p2.w},{p3.x,p3.y,p3.z,p3.w}};
        float rt[4][4] = {{o0.x,o0.y,o0.z,o0.w},{o1.x,o1.y,o1.z,o1.w},
                          {o2.x,o2.y,o2.z,o2.w},{o3.x,o3.y,o3.z,o3.w}};
#pragma unroll
        for (int i = 0; i < 4; i++)
#pragma unroll
            for (int j2 = 0; j2 < 4; j2++) { L[i][j2] = lt[i][j2]; R[i][j2] = rt[i][j2]; }
    }

    // tile rows 2u, 2u+1:  tile[a][b] = -(sum_k L[k][a]*R[k][b])
    float4* tdst = reinterpret_cast<float4*>(g_tile + (size_t)e * 16);
#pragma unroll
    for (int ai = 0; ai < 2; ai++) {
        int a = 2 * (int)u + ai;
        float4 p;
        p.x = -(L[0][a]*R[0][0] + L[1][a]*R[1][0] + L[2][a]*R[2][0] + L[3][a]*R[3][0]);
        p.y = -(L[0][a]*R[0][1] + L[1][a]*R[1][1] + L[2][a]*R[2][1] + L[3][a]*R[3][1]);
        p.z = -(L[0][a]*R[0][2] + L[1][a]*R[1][2] + L[2][a]*R[2][2] + L[3][a]*R[3][2]);
        p.w = -(L[0][a]*R[0][3] + L[1][a]*R[1][3] + L[2][a]*R[2][3] + L[3][a]*R[3][3]);
        tdst[a] = p;
    }

    // key for this thread's block
    unsigned long long key = u
        ? (((unsigned long long)c << 44) | ((unsigned long long)r << 22)
           | (2ull << 20) | (unsigned long long)e)
        : (((unsigned long long)r << 44) | ((unsigned long long)c << 22)
           | (1ull << 20) | (unsigned long long)e);
    g_key[slot] = key;
}

// Warp-per-node two-phase rank sort (rank-only O(cnt^2/32) + O(cnt) finish).
__global__ void k_sort() {
    unsigned gw = (blockIdx.x * blockDim.x + threadIdx.x) >> 5;
    int lane = threadIdx.x & 31;
    int wloc = (int)(threadIdx.x >> 5);
    __shared__ unsigned long long sIn[4][MAXL];
    __shared__ unsigned long long sOut[4][MAXL];
    if (gw >= NN) return;
    unsigned off = g_off[gw];
    int cnt = (int)(g_off[gw + 1] - off);

    if (cnt <= MAXL) {
        unsigned long long* bin  = sIn[wloc];
        unsigned long long* bout = sOut[wloc];
        for (int i = lane; i < cnt; i += 32) bin[i] = g_key[off + i];
        __syncwarp();
        for (int i = lane; i < cnt; i += 32) {
            unsigned long long x = bin[i];
            int rank = 0;
#pragma unroll 4
            for (int q = 0; q < cnt; q++) rank += (bin[q] < x);
            bout[rank] = x;
        }
        __syncwarp();
        for (int i = lane; i < cnt; i += 32) {
            unsigned long long x = bout[i];
            g_key[off + i] = x;
            unsigned long long tx = x >> 22;
            int lo = i, hi = i;
            while (lo > 0 && (bout[lo - 1] >> 22) == tx) lo--;
            while (hi + 1 < cnt && (bout[hi + 1] >> 22) == tx) hi++;
            g_run[off + i] = ((unsigned)(hi - lo + 1) << 16) | (unsigned)(i - lo);
        }
    } else if (lane == 0) {
        // safety fallback; never triggers for this dataset
        for (int i = 1; i < cnt; i++) {
            unsigned long long x = g_key[off + i];
            int j = i - 1;
            while (j >= 0 && g_key[off + j] > x) { g_key[off + j + 1] = g_key[off + j]; j--; }
            g_key[off + j + 1] = x;
        }
        int i = 0;
        while (i < cnt) {
            unsigned long long t = g_key[off + i] >> 22;
            int j = i + 1;
            while (j < cnt && (g_key[off + j] >> 22) == t) j++;
            unsigned m = (unsigned)(j - i);
            for (int q = i; q < j; q++)
                g_run[off + q] = (m << 16) | (unsigned)(q - i);
            i = j;
        }
    }
}

// Emit: one thread per (block slot, a). Edge values come precomputed from
// g_tile: cat1 thread a reads tile row a (one float4); cat2 thread a reads
// tile column a (4 scalars). The 4 threads of a block collectively touch
// exactly the 64B tile.
__global__ void k_emit(float* __restrict__ out) {
    unsigned tid = blockIdx.x * blockDim.x + threadIdx.x;
    if (tid >= (unsigned)NBLK * 4u) return;
    unsigned s = tid >> 2;
    int a = (int)(tid & 3u);

    unsigned long long key = g_key[s];
    unsigned node = (unsigned)(key >> 44);
    unsigned t    = (unsigned)(key >> 22) & 0x3FFFFFu;
    int      cat  = (int)((key >> 20) & 3ull);
    unsigned e    = (unsigned)(key & 0xFFFFFull);

    unsigned off = g_off[node];
    unsigned cnt = g_off[node + 1] - off;
    unsigned k   = s - off;

    float4 v;
    if (cat == 0) {
        const float* tri = g_diag + (size_t)node * 12;
        float vb[4];
#pragma unroll
        for (int b = 0; b < 4; b++) {
            int i2 = a < b ? a : b;
            int j2 = a < b ? b : a;
            vb[b] = tri[i2*4 + j2 - ((i2*(i2+1)) >> 1)];
        }
        v = make_float4(vb[0], vb[1], vb[2], vb[3]);
    } else if (cat == 1) {
        v = *reinterpret_cast<const float4*>(g_tile + (size_t)e * 16 + a * 4);
    } else {
        const float* tp = g_tile + (size_t)e * 16 + a;   // column a, stride 4
        v = make_float4(tp[0], tp[4], tp[8], tp[12]);
    }

    unsigned run = g_run[s];
    unsigned m = run >> 16;
    unsigned j = run & 0xFFFFu;
    float rowv = (float)(node * 4 + a);
    float cb   = (float)(t * 4u);

    if (m == 1u) {
        // fast path: 4 contiguous entries, float4 stores
        unsigned g = off * 16u + (unsigned)a * cnt * 4u + k * 4u;   // 4-aligned
        float4* rows = reinterpret_cast<float4*>(out);
        float4* cols = reinterpret_cast<float4*>(out + (size_t)NENT);
        float4* vals = reinterpret_cast<float4*>(out + (size_t)2 * NENT);
        rows[g >> 2] = make_float4(rowv, rowv, rowv, rowv);
        cols[g >> 2] = make_float4(cb, cb + 1.0f, cb + 2.0f, cb + 3.0f);
        vals[g >> 2] = v;
    } else {
        // rare path: blocks sharing t interleave by b with stride m
        unsigned k0 = k - j;
        size_t base = (size_t)off * 16u + (size_t)a * cnt * 4u + (size_t)k0 * 4u + j;
        float* rows = out;
        float* cols = out + (size_t)NENT;
        float* vals = out + (size_t)2 * NENT;
        float vb[4] = {v.x, v.y, v.z, v.w};
#pragma unroll
        for (unsigned b = 0; b < 4; b++) {
            size_t pos = base + (size_t)b * m;
            rows[pos] = rowv;
            cols[pos] = cb + (float)b;
            vals[pos] = vb[b];
        }
    }
}

extern "C" void kernel_launch(void* const* d_in, const int* in_sizes, int n_in,
                              void* d_out, int out_size) {
    const float* maps = (const float*)d_in[0];
    const int*   ei   = (const int*)d_in[1];
    float*       out  = (float*)d_out;

    void *p_diag, *p_cnt;
    cudaGetSymbolAddress(&p_diag, g_diag);
    cudaGetSymbolAddress(&p_cnt, g_cnt);
    cudaMemsetAsync(p_diag, 0, sizeof(float) * NN * 12);
    cudaMemsetAsync(p_cnt, 0, sizeof(unsigned) * NN);

    k_count     <<<(NE + 255)/256, 256>>>(ei);
    k_scan1     <<<NSB, SCAN_B>>>();
    k_scan3     <<<(NN + 255)/256, 256>>>();
    k_fill_diag <<<(2*NE + 255)/256, 256>>>(maps, ei);
    k_sort      <<<(NN*32 + 127)/128, 128>>>();
    {
        unsigned total = (unsigned)NBLK * 4u;
        k_emit  <<<(total + 255)/256, 256>>>(out);
    }
    (void)in_sizes; (void)n_in; (void)out_size;
}